// round 2
// baseline (speedup 1.0000x reference)
#include <cuda_runtime.h>
#include <cstdint>

// Problem constants
#define B_   128
#define F_   64
#define R_   4
#define D0_  2048
#define D1_  512
#define KTOT (D0_ * D1_)   // 1048576 (same for both params)
#define CHUNK 8192         // K elements per CTA
#define KT    32           // K-tile per iteration

// out[b,f] = sum_{i,j,r} jac[b,i,j] * Ua[i,r,f] * Ub[j,r,f]
// = GEMM: out[b,f] += sum_k jac[b,k] * V[k,f],  k = i*M2 + j,
//   V[k,f] = sum_r Ua[i,r,f]*Ub[j,r,f]

__device__ __forceinline__ uint32_t f2tf32(float x) {
    uint32_t r;
    asm("cvt.rna.tf32.f32 %0, %1;" : "=r"(r) : "f"(x));
    return r;
}

__device__ __forceinline__ void mma_tf32(float c[4], const uint32_t a[4],
                                         uint32_t b0, uint32_t b1) {
    asm volatile(
        "mma.sync.aligned.m16n8k8.row.col.f32.tf32.tf32.f32 "
        "{%0,%1,%2,%3}, {%4,%5,%6,%7}, {%8,%9}, {%0,%1,%2,%3};"
        : "+f"(c[0]), "+f"(c[1]), "+f"(c[2]), "+f"(c[3])
        : "r"(a[0]), "r"(a[1]), "r"(a[2]), "r"(a[3]), "r"(b0), "r"(b1));
}

__global__ void zero_out_kernel(float* out) {
    out[blockIdx.x * 256 + threadIdx.x] = 0.0f;
}

// M2 = extent of the j (contiguous) dim of jac; NI = CHUNK/M2 i-rows per CTA
template <int M2>
__global__ void __launch_bounds__(256, 2)
hora_kernel(const float* __restrict__ jac,   // [B, M1, M2] -> [B, KTOT]
            const float* __restrict__ Ua,    // [M1, R, F]
            const float* __restrict__ Ub,    // [M2, R, F]
            float* __restrict__ out)         // [B, F]
{
    constexpr int NI = CHUNK / M2;           // 16 (M2=512) or 4 (M2=2048)
    constexpr int AS_STRIDE = KT + 4;        // 36: (36g+t)%32 = 4g+t -> conflict-free
    constexpr int VS_STRIDE = F_ + 8;        // 72: (72t+g)%32 = 8t+g -> conflict-free

    __shared__ uint32_t As[B_ * AS_STRIDE];      // 128*36*4 = 18432 B (tf32 bits)
    __shared__ uint32_t Vs[KT * VS_STRIDE];      // 32*72*4  =  9216 B (tf32 bits)
    __shared__ float    Uas[16 * R_ * F_];       // up to 16 rows * 256 = 16384 B

    const int tid  = threadIdx.x;            // 256 threads
    const int wid  = tid >> 5;
    const int lane = tid & 31;
    const int g    = lane >> 2;              // 0..7
    const int t4   = lane & 3;               // 0..3
    const int wm   = (wid & 3) * 32;         // warp M offset (4 warps over 128 rows)
    const int wn   = (wid >> 2) * 32;        // warp N offset (2 warps over 64 cols)

    const size_t k0 = (size_t)blockIdx.x * CHUNK;
    const int    i0 = (int)(k0 / M2);

    // Preload this CTA's Ua rows (NI * 256 contiguous floats)
    for (int idx = tid; idx < NI * R_ * F_; idx += 256)
        Uas[idx] = Ua[(size_t)i0 * (R_ * F_) + idx];
    __syncthreads();

    float acc[2][4][4];
    #pragma unroll
    for (int m = 0; m < 2; m++)
        #pragma unroll
        for (int n = 0; n < 4; n++)
            #pragma unroll
            for (int e = 0; e < 4; e++)
                acc[m][n][e] = 0.0f;

    // Per-thread staging assignments
    const int arow = tid >> 1;               // As: 2 threads per row of 32 floats
    const int aqb  = (tid & 1) * 4;          // 4 float4 quads each
    const int vkk  = tid >> 3;               // Vs: 8 threads per k
    const int vfb  = (tid & 7) * 8;          // 8 f-values each

    for (int tile = 0; tile < CHUNK / KT; ++tile) {
        const int koff = tile * KT;
        const int il   = koff / M2;          // local i index (compile-time shift)
        const int jb   = koff % M2;          // j base (KT-tile never crosses an i row)

        // ---- Stage jac tile -> As (tf32) ----
        {
            const float4* src = reinterpret_cast<const float4*>(
                jac + (size_t)arow * KTOT + k0 + koff);
            #pragma unroll
            for (int q = 0; q < 4; q++) {
                float4 v = src[aqb + q];
                uint32_t* dst = &As[arow * AS_STRIDE + (aqb + q) * 4];
                uint4 w;
                w.x = f2tf32(v.x); w.y = f2tf32(v.y);
                w.z = f2tf32(v.z); w.w = f2tf32(v.w);
                *reinterpret_cast<uint4*>(dst) = w;
            }
        }

        // ---- Compute V tile -> Vs (tf32) ----
        {
            const float* ub = Ub + (size_t)(jb + vkk) * (R_ * F_) + vfb;
            const float* ua = &Uas[il * (R_ * F_) + vfb];
            float v[8];
            #pragma unroll
            for (int e = 0; e < 8; e++) v[e] = 0.0f;
            #pragma unroll
            for (int r = 0; r < R_; r++) {
                float4 ua0 = *reinterpret_cast<const float4*>(ua + r * F_);
                float4 ua1 = *reinterpret_cast<const float4*>(ua + r * F_ + 4);
                float4 ub0 = *reinterpret_cast<const float4*>(ub + r * F_);
                float4 ub1 = *reinterpret_cast<const float4*>(ub + r * F_ + 4);
                v[0] += ua0.x * ub0.x; v[1] += ua0.y * ub0.y;
                v[2] += ua0.z * ub0.z; v[3] += ua0.w * ub0.w;
                v[4] += ua1.x * ub1.x; v[5] += ua1.y * ub1.y;
                v[6] += ua1.z * ub1.z; v[7] += ua1.w * ub1.w;
            }
            uint32_t* dst = &Vs[vkk * VS_STRIDE + vfb];
            uint4 w0, w1;
            w0.x = f2tf32(v[0]); w0.y = f2tf32(v[1]);
            w0.z = f2tf32(v[2]); w0.w = f2tf32(v[3]);
            w1.x = f2tf32(v[4]); w1.y = f2tf32(v[5]);
            w1.z = f2tf32(v[6]); w1.w = f2tf32(v[7]);
            *reinterpret_cast<uint4*>(dst)     = w0;
            *reinterpret_cast<uint4*>(dst + 4) = w1;
        }
        __syncthreads();

        // ---- MMA: 4 k-steps of 8 ----
        #pragma unroll
        for (int ks = 0; ks < 4; ks++) {
            uint32_t a[2][4];
            #pragma unroll
            for (int m = 0; m < 2; m++) {
                const int r0 = wm + m * 16 + g;
                const int c0 = ks * 8 + t4;
                a[m][0] = As[r0 * AS_STRIDE + c0];
                a[m][1] = As[(r0 + 8) * AS_STRIDE + c0];
                a[m][2] = As[r0 * AS_STRIDE + c0 + 4];
                a[m][3] = As[(r0 + 8) * AS_STRIDE + c0 + 4];
            }
            #pragma unroll
            for (int n = 0; n < 4; n++) {
                const int col = wn + n * 8 + g;
                uint32_t b0 = Vs[(ks * 8 + t4) * VS_STRIDE + col];
                uint32_t b1 = Vs[(ks * 8 + t4 + 4) * VS_STRIDE + col];
                mma_tf32(acc[0][n], a[0], b0, b1);
                mma_tf32(acc[1][n], a[1], b0, b1);
            }
        }
        __syncthreads();
    }

    // ---- Epilogue: accumulate into out[b,f] ----
    #pragma unroll
    for (int m = 0; m < 2; m++) {
        #pragma unroll
        for (int n = 0; n < 4; n++) {
            const int row = wm + m * 16 + g;
            const int col = wn + n * 8 + t4 * 2;
            atomicAdd(&out[row * F_ + col],           acc[m][n][0]);
            atomicAdd(&out[row * F_ + col + 1],       acc[m][n][1]);
            atomicAdd(&out[(row + 8) * F_ + col],     acc[m][n][2]);
            atomicAdd(&out[(row + 8) * F_ + col + 1], acc[m][n][3]);
        }
    }
}

extern "C" void kernel_launch(void* const* d_in, const int* in_sizes, int n_in,
                              void* d_out, int out_size) {
    const float* jac1 = (const float*)d_in[0];  // [128, 2048, 512]
    const float* jac2 = (const float*)d_in[1];  // [128, 512, 2048]
    const float* U1a  = (const float*)d_in[2];  // [2048, 4, 64]
    const float* U1b  = (const float*)d_in[3];  // [512, 4, 64]
    const float* U2a  = (const float*)d_in[4];  // [512, 4, 64]
    const float* U2b  = (const float*)d_in[5];  // [2048, 4, 64]
    float* out = (float*)d_out;                 // [128, 64]

    zero_out_kernel<<<(B_ * F_) / 256, 256>>>(out);

    // param 1: jac1 [B, i=2048, j=512]  -> M2 = 512
    hora_kernel<512><<<KTOT / CHUNK, 256>>>(jac1, U1a, U1b, out);
    // param 2: jac2 [B, i=512, j=2048]  -> M2 = 2048
    hora_kernel<2048><<<KTOT / CHUNK, 256>>>(jac2, U2a, U2b, out);
}

// round 3
// speedup vs baseline: 1.6623x; 1.6623x over previous
#include <cuda_runtime.h>
#include <cstdint>

#define B_    128
#define F_    64
#define R_    4
#define KTOT  (2048 * 512)     // 1048576
#define CHUNK 8192             // K per CTA
#define KT    32               // K per tile
#define NTILE (CHUNK / KT)     // 256

// out[b,f] = sum_k jac[b,k] * V[k,f],  k=(i,j),  V[k,f] = sum_r Ua[i,r,f]*Ub[j,r,f]

__device__ __forceinline__ uint32_t f2tf32(float x) {
    uint32_t r;
    asm("cvt.rna.tf32.f32 %0, %1;" : "=r"(r) : "f"(x));
    return r;
}

__device__ __forceinline__ void mma_tf32(float c[4], const uint32_t a[4],
                                         uint32_t b0, uint32_t b1) {
    asm volatile(
        "mma.sync.aligned.m16n8k8.row.col.f32.tf32.tf32.f32 "
        "{%0,%1,%2,%3}, {%4,%5,%6,%7}, {%8,%9}, {%0,%1,%2,%3};"
        : "+f"(c[0]), "+f"(c[1]), "+f"(c[2]), "+f"(c[3])
        : "r"(a[0]), "r"(a[1]), "r"(a[2]), "r"(a[3]), "r"(b0), "r"(b1));
}

__global__ void zero_out_kernel(float* out) {
    out[blockIdx.x * 256 + threadIdx.x] = 0.0f;
}

// Dynamic smem layout (uint32 units):
//   As : [0, 8192)      2 x 128 x 32 tf32, swizzled  (32 KB)
//   Vs : [8192, 12288)  2 x 32 x 64 tf32, swizzled   (16 KB)
//   Uas: [12288, 16384) up to 16 rows x 256 floats   (16 KB)
#define SMEM_U32 16384

template <int M2>
__device__ __forceinline__ void hora_body(
    const float* __restrict__ jac, const float* __restrict__ Ua,
    const float* __restrict__ Ub, float* __restrict__ out, uint32_t* sm)
{
    constexpr int NI = CHUNK / M2;          // 16 (M2=512) or 4 (M2=2048)
    uint32_t* As  = sm;
    uint32_t* Vs  = sm + 8192;
    float*    Uas = reinterpret_cast<float*>(sm + 12288);

    const int tid  = threadIdx.x;
    const int wid  = tid >> 5;
    const int lane = tid & 31;
    const int g    = lane >> 2;             // 0..7
    const int t4   = lane & 3;              // 0..3
    const int wm   = (wid & 3) * 32;
    const int wn   = (wid >> 2) * 32;

    const size_t k0 = (size_t)blockIdx.x * CHUNK;
    const int    i0 = blockIdx.x * NI;

    // Preload this CTA's Ua rows (NI * 256 floats, L2)
    for (int idx = tid; idx < NI * 256; idx += 256)
        Uas[idx] = Ua[(size_t)i0 * 256 + idx];

    // Per-thread staging roles
    const int arow = tid >> 1;              // jac row (2 threads/row)
    const int aq0  = (tid & 1) * 4;         // first of 4 float4 quads
    const int vkk  = tid >> 3;              // V row (8 threads/row)
    const int vfb  = (tid & 7) * 8;         // 8 f-values

    float acc[2][4][4];
    #pragma unroll
    for (int m = 0; m < 2; m++)
        #pragma unroll
        for (int n = 0; n < 4; n++)
            #pragma unroll
            for (int e = 0; e < 4; e++) acc[m][n][e] = 0.0f;

    // Ub slice for current j-tile lives in registers across NI inner iters
    float ub[R_][8];

    #define LOAD_UB(JT) do {                                                  \
        const float* p_ = Ub + (size_t)((JT) * KT + vkk) * 256 + vfb;         \
        _Pragma("unroll")                                                     \
        for (int r_ = 0; r_ < R_; r_++) {                                     \
            float4 x0_ = *reinterpret_cast<const float4*>(p_ + r_ * 64);      \
            float4 x1_ = *reinterpret_cast<const float4*>(p_ + r_ * 64 + 4);  \
            ub[r_][0] = x0_.x; ub[r_][1] = x0_.y;                             \
            ub[r_][2] = x0_.z; ub[r_][3] = x0_.w;                             \
            ub[r_][4] = x1_.x; ub[r_][5] = x1_.y;                             \
            ub[r_][6] = x1_.z; ub[r_][7] = x1_.w;                             \
        }                                                                     \
    } while (0)

    #define LOAD_A(T, PF) do {                                                \
        int jt_ = (T) / NI, ii_ = (T) % NI;                                   \
        const float4* s_ = reinterpret_cast<const float4*>(                   \
            jac + (size_t)arow * KTOT + k0 + (size_t)ii_ * M2 + jt_ * KT);    \
        _Pragma("unroll")                                                     \
        for (int q_ = 0; q_ < 4; q_++) (PF)[q_] = s_[aq0 + q_];               \
    } while (0)

    #define STAGE_A(BUF, PF) do {                                             \
        uint32_t* base_ = As + (BUF) * 4096 + arow * 32;                      \
        _Pragma("unroll")                                                     \
        for (int q_ = 0; q_ < 4; q_++) {                                      \
            int cs_ = ((aq0 + q_) * 4) ^ ((arow & 7) * 4);                    \
            uint4 w_;                                                         \
            w_.x = f2tf32((PF)[q_].x); w_.y = f2tf32((PF)[q_].y);             \
            w_.z = f2tf32((PF)[q_].z); w_.w = f2tf32((PF)[q_].w);             \
            *reinterpret_cast<uint4*>(base_ + cs_) = w_;                      \
        }                                                                     \
    } while (0)

    #define STAGE_V(BUF, II) do {                                             \
        const float* ua_ = Uas + (II) * 256 + vfb;                            \
        float v_[8];                                                          \
        _Pragma("unroll")                                                     \
        for (int e_ = 0; e_ < 8; e_++) v_[e_] = 0.0f;                         \
        _Pragma("unroll")                                                     \
        for (int r_ = 0; r_ < R_; r_++) {                                     \
            float4 a0_ = *reinterpret_cast<const float4*>(ua_ + r_ * 64);     \
            float4 a1_ = *reinterpret_cast<const float4*>(ua_ + r_ * 64 + 4); \
            v_[0] += a0_.x * ub[r_][0]; v_[1] += a0_.y * ub[r_][1];           \
            v_[2] += a0_.z * ub[r_][2]; v_[3] += a0_.w * ub[r_][3];           \
            v_[4] += a1_.x * ub[r_][4]; v_[5] += a1_.y * ub[r_][5];           \
            v_[6] += a1_.z * ub[r_][6]; v_[7] += a1_.w * ub[r_][7];           \
        }                                                                     \
        uint32_t* base_ = Vs + (BUF) * 2048 + vkk * 64;                       \
        int cs_ = vfb ^ ((vkk & 7) * 8);                                      \
        uint4 w0_, w1_;                                                       \
        w0_.x = f2tf32(v_[0]); w0_.y = f2tf32(v_[1]);                         \
        w0_.z = f2tf32(v_[2]); w0_.w = f2tf32(v_[3]);                         \
        w1_.x = f2tf32(v_[4]); w1_.y = f2tf32(v_[5]);                         \
        w1_.z = f2tf32(v_[6]); w1_.w = f2tf32(v_[7]);                         \
        *reinterpret_cast<uint4*>(base_ + cs_)     = w0_;                     \
        *reinterpret_cast<uint4*>(base_ + cs_ + 4) = w1_;                     \
    } while (0)

    // ---- Prologue: tile 0 ----
    {
        float4 pf[4];
        LOAD_UB(0);
        LOAD_A(0, pf);
        STAGE_A(0, pf);
        __syncthreads();   // Uas preload complete before STAGE_V reads it
        STAGE_V(0, 0);
        __syncthreads();
    }

    // ---- Main pipelined loop ----
    for (int t = 0; t < NTILE; t++) {
        const int buf = t & 1;
        const int tn  = t + 1;
        const bool hn = tn < NTILE;
        float4 pfn[4];
        if (hn) {
            LOAD_A(tn, pfn);               // prefetch next jac tile (DRAM)
            if ((tn % NI) == 0) LOAD_UB(tn / NI);   // new j-tile slice (L2)
        }

        // MMA on current buffers
        {
            const uint32_t* Ab = As + buf * 4096;
            const uint32_t* Vb = Vs + buf * 2048;
            #pragma unroll
            for (int ks = 0; ks < 4; ks++) {
                uint32_t a[2][4];
                #pragma unroll
                for (int m = 0; m < 2; m++) {
                    const int r0 = wm + m * 16 + g;
                    const int r1 = r0 + 8;
                    const int c0 = ks * 8 + t4;
                    const int c1 = c0 + 4;
                    const int sw = (g) * 4;          // r0&7 == r1&7 == g
                    a[m][0] = Ab[r0 * 32 + (c0 ^ sw)];
                    a[m][1] = Ab[r1 * 32 + (c0 ^ sw)];
                    a[m][2] = Ab[r0 * 32 + (c1 ^ sw)];
                    a[m][3] = Ab[r1 * 32 + (c1 ^ sw)];
                }
                const int kr0 = ks * 8 + t4;
                const int kr1 = kr0 + 4;
                #pragma unroll
                for (int n = 0; n < 4; n++) {
                    const int col = wn + n * 8 + g;
                    uint32_t b0 = Vb[kr0 * 64 + (col ^ ((kr0 & 7) * 8))];
                    uint32_t b1 = Vb[kr1 * 64 + (col ^ ((kr1 & 7) * 8))];
                    mma_tf32(acc[0][n], a[0], b0, b1);
                    mma_tf32(acc[1][n], a[1], b0, b1);
                }
            }
        }

        if (hn) {
            STAGE_A(buf ^ 1, pfn);
            STAGE_V(buf ^ 1, tn % NI);
        }
        __syncthreads();
    }

    // ---- Epilogue: disjoint-per-warp accumulate into out[b,f] ----
    #pragma unroll
    for (int m = 0; m < 2; m++) {
        #pragma unroll
        for (int n = 0; n < 4; n++) {
            const int row = wm + m * 16 + g;
            const int col = wn + n * 8 + t4 * 2;
            atomicAdd(&out[row * F_ + col],           acc[m][n][0]);
            atomicAdd(&out[row * F_ + col + 1],       acc[m][n][1]);
            atomicAdd(&out[(row + 8) * F_ + col],     acc[m][n][2]);
            atomicAdd(&out[(row + 8) * F_ + col + 1], acc[m][n][3]);
        }
    }
    #undef LOAD_UB
    #undef LOAD_A
    #undef STAGE_A
    #undef STAGE_V
}

__global__ void __launch_bounds__(256, 2)
hora_kernel(const float* __restrict__ jac1, const float* __restrict__ U1a,
            const float* __restrict__ U1b,  const float* __restrict__ jac2,
            const float* __restrict__ U2a,  const float* __restrict__ U2b,
            float* __restrict__ out)
{
    extern __shared__ uint32_t smbuf[];
    if (blockIdx.y == 0)
        hora_body<512>(jac1, U1a, U1b, out, smbuf);   // jac1 [B, 2048, 512]
    else
        hora_body<2048>(jac2, U2a, U2b, out, smbuf);  // jac2 [B, 512, 2048]
}

extern "C" void kernel_launch(void* const* d_in, const int* in_sizes, int n_in,
                              void* d_out, int out_size) {
    const float* jac1 = (const float*)d_in[0];
    const float* jac2 = (const float*)d_in[1];
    const float* U1a  = (const float*)d_in[2];
    const float* U1b  = (const float*)d_in[3];
    const float* U2a  = (const float*)d_in[4];
    const float* U2b  = (const float*)d_in[5];
    float* out = (float*)d_out;

    cudaFuncSetAttribute(hora_kernel,
                         cudaFuncAttributeMaxDynamicSharedMemorySize,
                         SMEM_U32 * 4);

    zero_out_kernel<<<(B_ * F_) / 256, 256>>>(out);
    hora_kernel<<<dim3(KTOT / CHUNK, 2), 256, SMEM_U32 * 4>>>(
        jac1, U1a, U1b, jac2, U2a, U2b, out);
}